// round 16
// baseline (speedup 1.0000x reference)
#include <cuda_runtime.h>
#include <cuda_fp16.h>
#include <math.h>
#include <stdint.h>

// ---------------------------------------------------------------------------
// CHI block on GB300 (sm_103 PTX => mma.sync HMMA path).
// R16: batched mega-launches (z-indexed) to kill kernel-boundary tails:
// 1x ln4, 1x wconv6, 1x qkv(6 GEMMs), 1x attn(2 branches), 1x proj(2),
// fused ln16_sum. GEMM core = R15 best (128x128, 4 warps, 3-stage, 2 CTA/SM).
// ---------------------------------------------------------------------------

#define Bsz   8
#define Nseq  1024
#define Cdim  1024
#define HidD  4096
#define NH    16
#define HD    64
#define Mrows (Bsz * Nseq)           // 8192

typedef __half fp16;

// ---------------- scratch (static device globals; no allocs) ---------------
__device__ fp16 g_wT  [16u << 20];                     // transposed fp16 weights
__device__ fp16 g_ln  [4][(size_t)Mrows * Cdim];       // ln11,ln12,ln21,ln23 out
__device__ fp16 g_q   [2][(size_t)Mrows * Cdim];
__device__ fp16 g_kv  [2][(size_t)Mrows * 2 * Cdim];
__device__ fp16 g_ao  [2][(size_t)Mrows * Cdim];
__device__ fp16 g_h   [(size_t)Mrows * HidD];
__device__ fp16 g_res16[(size_t)Mrows * Cdim];
__device__ fp16 g_br2 [(size_t)Mrows * Cdim];

// ------------------------------ PTX helpers --------------------------------
__device__ __forceinline__ uint32_t smem_u32(const void* p) {
    uint32_t a;
    asm("{ .reg .u64 t; cvta.to.shared.u64 t, %1; cvt.u32.u64 %0, t; }"
        : "=r"(a) : "l"(p));
    return a;
}

__device__ __forceinline__ void cp16(uint32_t dst, const void* src) {
    asm volatile("cp.async.cg.shared.global [%0], [%1], 16;\n"
                 :: "r"(dst), "l"(src) : "memory");
}
#define CP_COMMIT() asm volatile("cp.async.commit_group;\n" ::: "memory")
#define CP_WAIT1()  asm volatile("cp.async.wait_group 1;\n" ::: "memory")
#define CP_WAIT0()  asm volatile("cp.async.wait_group 0;\n" ::: "memory")

__device__ __forceinline__ void ldsm4(uint32_t (&r)[4], uint32_t addr) {
    asm volatile("ldmatrix.sync.aligned.m8n8.x4.shared.b16 {%0,%1,%2,%3}, [%4];"
        : "=r"(r[0]), "=r"(r[1]), "=r"(r[2]), "=r"(r[3]) : "r"(addr));
}
__device__ __forceinline__ void ldsm4t(uint32_t (&r)[4], uint32_t addr) {
    asm volatile("ldmatrix.sync.aligned.m8n8.x4.trans.shared.b16 {%0,%1,%2,%3}, [%4];"
        : "=r"(r[0]), "=r"(r[1]), "=r"(r[2]), "=r"(r[3]) : "r"(addr));
}

__device__ __forceinline__ void mma16816(float (&d)[4], const uint32_t (&a)[4],
                                         uint32_t b0, uint32_t b1) {
    asm volatile(
        "mma.sync.aligned.m16n8k16.row.col.f32.f16.f16.f32 "
        "{%0,%1,%2,%3}, {%4,%5,%6,%7}, {%8,%9}, {%0,%1,%2,%3};"
        : "+f"(d[0]), "+f"(d[1]), "+f"(d[2]), "+f"(d[3])
        : "r"(a[0]), "r"(a[1]), "r"(a[2]), "r"(a[3]), "r"(b0), "r"(b1));
}

__device__ __forceinline__ uint32_t pack_h2(float a, float b) {
    __half2 v = __floats2half2_rn(a, b);
    return *reinterpret_cast<uint32_t*>(&v);
}

// --------------------------- arg structs ------------------------------------
struct Ln4Args {
    const float* x[4];
    const float* g[4];
    const float* b[4];
    fp16* o[4];
};
struct W6Args {
    const float* w[6];
    fp16* d[6];
};
struct QkvArgs {
    const fp16* A[6];
    const fp16* B[6];
    fp16* out[6];
    int ostride[6];
};
struct AttnArgs {
    const fp16* q[2];
    const fp16* kv[2];
    fp16* o[2];
};
struct ProjArgs {
    const fp16* A[2];
    const fp16* B[2];
    const float* bias[2];
    const float* resF;     // x1, z=0 only
    fp16* out[2];
};

// ------------------------------ LayerNorm x4 --------------------------------
__global__ __launch_bounds__(256) void ln4_kernel(Ln4Args a)
{
    int which = blockIdx.x >> 13;          // 8192 rows per LN
    int row   = blockIdx.x & 8191;
    int t     = threadIdx.x;
    const float4* xr = (const float4*)(a.x[which] + (size_t)row * Cdim);
    float4 v = xr[t];
    float s  = v.x + v.y + v.z + v.w;
    float s2 = v.x*v.x + v.y*v.y + v.z*v.z + v.w*v.w;

    __shared__ float sa[8], sb_[8];
    #pragma unroll
    for (int o = 16; o > 0; o >>= 1) {
        s  += __shfl_down_sync(0xffffffffu, s,  o);
        s2 += __shfl_down_sync(0xffffffffu, s2, o);
    }
    int w = t >> 5, l = t & 31;
    if (l == 0) { sa[w] = s; sb_[w] = s2; }
    __syncthreads();
    if (w == 0) {
        s  = (l < 8) ? sa[l] : 0.f;
        s2 = (l < 8) ? sb_[l] : 0.f;
        #pragma unroll
        for (int o = 4; o > 0; o >>= 1) {
            s  += __shfl_down_sync(0xffffffffu, s,  o);
            s2 += __shfl_down_sync(0xffffffffu, s2, o);
        }
        if (l == 0) { sa[0] = s; sb_[0] = s2; }
    }
    __syncthreads();
    float mean = sa[0] * (1.0f / Cdim);
    float var  = sb_[0] * (1.0f / Cdim) - mean * mean;
    float r    = rsqrtf(var + 1e-5f);

    float4 g4 = ((const float4*)a.g[which])[t];
    float4 b4 = ((const float4*)a.b[which])[t];
    float o0 = (v.x - mean) * r * g4.x + b4.x;
    float o1 = (v.y - mean) * r * g4.y + b4.y;
    float o2 = (v.z - mean) * r * g4.z + b4.z;
    float o3 = (v.w - mean) * r * g4.w + b4.w;

    size_t idx = (size_t)row * Cdim + t * 4;
    fp16* ohi = a.o[which];
    *(__half2*)(ohi + idx)     = __floats2half2_rn(o0, o1);
    *(__half2*)(ohi + idx + 2) = __floats2half2_rn(o2, o3);
}

// -------------------- fused residual-sum + LayerNorm ------------------------
// s = res16 + br2 (fp32); res16 <- fp16(s); ohi <- fp16(LN(s))
__global__ __launch_bounds__(256) void ln16_sum_kernel(
    fp16* __restrict__ res16, const fp16* __restrict__ br2,
    const float* __restrict__ gma, const float* __restrict__ bta,
    fp16* __restrict__ ohi)
{
    int row = blockIdx.x;
    int t   = threadIdx.x;
    size_t base = (size_t)row * Cdim + t * 4;
    __half2 a0 = *(__half2*)(res16 + base),     a1 = *(__half2*)(res16 + base + 2);
    __half2 b0 = *(const __half2*)(br2 + base), b1 = *(const __half2*)(br2 + base + 2);
    float v0 = __low2float(a0) + __low2float(b0);
    float v1 = __high2float(a0) + __high2float(b0);
    float v2 = __low2float(a1) + __low2float(b1);
    float v3 = __high2float(a1) + __high2float(b1);
    // write summed residual back
    *(__half2*)(res16 + base)     = __floats2half2_rn(v0, v1);
    *(__half2*)(res16 + base + 2) = __floats2half2_rn(v2, v3);

    float s  = v0 + v1 + v2 + v3;
    float s2 = v0*v0 + v1*v1 + v2*v2 + v3*v3;

    __shared__ float sa[8], sb_[8];
    #pragma unroll
    for (int o = 16; o > 0; o >>= 1) {
        s  += __shfl_down_sync(0xffffffffu, s,  o);
        s2 += __shfl_down_sync(0xffffffffu, s2, o);
    }
    int w = t >> 5, l = t & 31;
    if (l == 0) { sa[w] = s; sb_[w] = s2; }
    __syncthreads();
    if (w == 0) {
        s  = (l < 8) ? sa[l] : 0.f;
        s2 = (l < 8) ? sb_[l] : 0.f;
        #pragma unroll
        for (int o = 4; o > 0; o >>= 1) {
            s  += __shfl_down_sync(0xffffffffu, s,  o);
            s2 += __shfl_down_sync(0xffffffffu, s2, o);
        }
        if (l == 0) { sa[0] = s; sb_[0] = s2; }
    }
    __syncthreads();
    float mean = sa[0] * (1.0f / Cdim);
    float var  = sb_[0] * (1.0f / Cdim) - mean * mean;
    float r    = rsqrtf(var + 1e-5f);

    float4 g4 = ((const float4*)gma)[t];
    float4 b4 = ((const float4*)bta)[t];
    float o0 = (v0 - mean) * r * g4.x + b4.x;
    float o1 = (v1 - mean) * r * g4.y + b4.y;
    float o2 = (v2 - mean) * r * g4.z + b4.z;
    float o3 = (v3 - mean) * r * g4.w + b4.w;

    *(__half2*)(ohi + base)     = __floats2half2_rn(o0, o1);
    *(__half2*)(ohi + base + 2) = __floats2half2_rn(o2, o3);
}

// ----------------------- weight transpose (fp16 hi) ------------------------
__global__ __launch_bounds__(256) void wconv_kernel(
    const float* __restrict__ W, fp16* __restrict__ Whi, int K, int N)
{
    __shared__ float tile[32][33];
    int n0 = blockIdx.x * 32, k0 = blockIdx.y * 32;
    int tx = threadIdx.x & 31, ty = threadIdx.x >> 5;
    #pragma unroll
    for (int i = 0; i < 4; i++)
        tile[ty + i * 8][tx] = W[(size_t)(k0 + ty + i * 8) * N + n0 + tx];
    __syncthreads();
    #pragma unroll
    for (int i = 0; i < 4; i++) {
        int r = ty + i * 8;
        Whi[(size_t)(n0 + r) * K + k0 + tx] = __float2half_rn(tile[tx][r]);
    }
}

// six CxC weights in one launch (z = 0..5)
__global__ __launch_bounds__(256) void wconv6_kernel(W6Args a)
{
    const float* W = a.w[blockIdx.z];
    fp16* D = a.d[blockIdx.z];
    __shared__ float tile[32][33];
    int n0 = blockIdx.x * 32, k0 = blockIdx.y * 32;
    int tx = threadIdx.x & 31, ty = threadIdx.x >> 5;
    #pragma unroll
    for (int i = 0; i < 4; i++)
        tile[ty + i * 8][tx] = W[(size_t)(k0 + ty + i * 8) * Cdim + n0 + tx];
    __syncthreads();
    #pragma unroll
    for (int i = 0; i < 4; i++) {
        int r = ty + i * 8;
        D[(size_t)(n0 + r) * Cdim + k0 + tx] = __float2half_rn(tile[tx][r]);
    }
}

// --------------------------- GEMM core --------------------------------------
// 128x128 CTA tile, 128 threads = 4 warps (2m x 2n), warp tile 64x64,
// BK=64, 3-stage cp.async, one barrier/iter, 2 CTAs per SM.
#define G_STRIDE_B 144u
#define G_A_B      18432u
#define G_STAGE_B  36864u
#define GEMM_SMEM  (3 * 36864)

__device__ __forceinline__ void gemm_core(
    uint32_t sb, int t, int lane, int wid,
    const fp16* srcA, const fp16* srcB, int K, float (&acc)[4][8][4])
{
    auto load_stage = [&](int s) {
        uint32_t base = sb + (uint32_t)(s % 3) * G_STAGE_B;
        int k0 = s << 6;
        #pragma unroll
        for (int i = 0; i < 16; i++) {
            int idx = t + (i << 7);
            const fp16* src;
            uint32_t off;
            int cid;
            if (idx < 1024) { cid = idx;        src = srcA; off = 0; }
            else            { cid = idx - 1024; src = srcB; off = G_A_B; }
            int row = cid >> 3, c = cid & 7;
            cp16(base + off + (uint32_t)row * G_STRIDE_B + (uint32_t)c * 16u,
                 src + (size_t)row * K + k0 + c * 8);
        }
        CP_COMMIT();
    };

    load_stage(0);
    load_stage(1);
    const int S = K >> 6;
    const int wm = wid >> 1, wn = wid & 1;
    const uint32_t lrow = (uint32_t)(lane & 15);
    const uint32_t lc16 = (uint32_t)(lane >> 4) * 16u;
    const uint32_t aoff = ((uint32_t)(wm * 64) + lrow) * G_STRIDE_B + lc16;
    const uint32_t boff = ((uint32_t)(wn * 64) + lrow) * G_STRIDE_B + lc16;

    for (int s = 0; s < S; s++) {
        if (s + 1 < S) { CP_WAIT1(); }
        else           { CP_WAIT0(); }
        __syncthreads();
        uint32_t base = sb + (uint32_t)(s % 3) * G_STAGE_B;
        #pragma unroll
        for (int k16 = 0; k16 < 4; k16++) {
            uint32_t ko = (uint32_t)k16 * 32u;
            uint32_t ah[4][4], bf[4][4];
            #pragma unroll
            for (int f = 0; f < 4; f++)
                ldsm4(ah[f], base + aoff + (uint32_t)f * 16u * G_STRIDE_B + ko);
            #pragma unroll
            for (int g = 0; g < 4; g++)
                ldsm4(bf[g], base + G_A_B + boff + (uint32_t)g * 16u * G_STRIDE_B + ko);
            #pragma unroll
            for (int mi = 0; mi < 4; mi++)
                #pragma unroll
                for (int ni = 0; ni < 8; ni++)
                    mma16816(acc[mi][ni], ah[mi],
                             bf[ni >> 1][ni & 1], bf[ni >> 1][2 + (ni & 1)]);
        }
        if (s + 2 < S) load_stage(s + 2);
    }
}

// --------------------------- batched QKV GEMM -------------------------------
__global__ __launch_bounds__(128, 2) void qkv_tc(QkvArgs a)
{
    extern __shared__ char smem[];
    const uint32_t sb = smem_u32(smem);
    const int t = threadIdx.x, lane = t & 31, wid = t >> 5;
    const int bn = blockIdx.x, bm = blockIdx.y, z = blockIdx.z;

    const fp16* srcA = a.A[z] + (size_t)(bm * 128) * Cdim;
    const fp16* srcB = a.B[z] + (size_t)(bn * 128) * Cdim;

    float acc[4][8][4];
    #pragma unroll
    for (int mi = 0; mi < 4; mi++)
        #pragma unroll
        for (int ni = 0; ni < 8; ni++)
            #pragma unroll
            for (int j = 0; j < 4; j++) acc[mi][ni][j] = 0.f;

    gemm_core(sb, t, lane, wid, srcA, srcB, Cdim, acc);

    const int wm = wid >> 1, wn = wid & 1;
    const int r0 = bm * 128 + wm * 64 + (lane >> 2);
    const int c0 = bn * 128 + wn * 64 + (lane & 3) * 2;
    fp16* outp = a.out[z];
    const int ostride = a.ostride[z];
    #pragma unroll
    for (int mi = 0; mi < 4; mi++)
        #pragma unroll
        for (int rh = 0; rh < 2; rh++) {
            int row = r0 + mi * 16 + rh * 8;
            #pragma unroll
            for (int ni = 0; ni < 8; ni++) {
                int col = c0 + ni * 8;
                *(__half2*)(outp + (size_t)row * ostride + col) =
                    __floats2half2_rn(acc[mi][ni][2 * rh], acc[mi][ni][2 * rh + 1]);
            }
        }
}

// --------------------------- batched proj GEMM ------------------------------
__global__ __launch_bounds__(128, 2) void proj_tc(ProjArgs a)
{
    extern __shared__ char smem[];
    const uint32_t sb = smem_u32(smem);
    const int t = threadIdx.x, lane = t & 31, wid = t >> 5;
    const int bn = blockIdx.x, bm = blockIdx.y, z = blockIdx.z;

    const fp16* srcA = a.A[z] + (size_t)(bm * 128) * Cdim;
    const fp16* srcB = a.B[z] + (size_t)(bn * 128) * Cdim;

    float acc[4][8][4];
    #pragma unroll
    for (int mi = 0; mi < 4; mi++)
        #pragma unroll
        for (int ni = 0; ni < 8; ni++)
            #pragma unroll
            for (int j = 0; j < 4; j++) acc[mi][ni][j] = 0.f;

    gemm_core(sb, t, lane, wid, srcA, srcB, Cdim, acc);

    const int wm = wid >> 1, wn = wid & 1;
    const int r0 = bm * 128 + wm * 64 + (lane >> 2);
    const int c0 = bn * 128 + wn * 64 + (lane & 3) * 2;
    const float* bias = a.bias[z];
    fp16* outp = a.out[z];
    #pragma unroll
    for (int mi = 0; mi < 4; mi++)
        #pragma unroll
        for (int rh = 0; rh < 2; rh++) {
            int row = r0 + mi * 16 + rh * 8;
            #pragma unroll
            for (int ni = 0; ni < 8; ni++) {
                int col = c0 + ni * 8;
                float v0 = acc[mi][ni][2 * rh]     + bias[col];
                float v1 = acc[mi][ni][2 * rh + 1] + bias[col + 1];
                if (z == 0) {
                    const float* rp = a.resF + (size_t)row * Cdim + col;
                    v0 += rp[0]; v1 += rp[1];
                }
                *(__half2*)(outp + (size_t)row * Cdim + col) =
                    __floats2half2_rn(v0, v1);
            }
        }
}

// --------------------------- generic GEMM (fc1/fc2) -------------------------
#define GF_BIAS  1
#define GF_GELU  4
#define GF_HI    16
#define GF_RES16 32

__global__ __launch_bounds__(128, 2) void gemm_tc(
    const fp16* __restrict__ Ahi, const fp16* __restrict__ Bhi,
    const float* __restrict__ bias, const fp16* __restrict__ resH,
    float* __restrict__ outF, fp16* __restrict__ outHi,
    int M, int N, int K, int flags)
{
    extern __shared__ char smem[];
    const uint32_t sb = smem_u32(smem);
    const int t = threadIdx.x, lane = t & 31, wid = t >> 5;
    const int bn = blockIdx.x, bm = blockIdx.y;

    const fp16* srcA = Ahi + (size_t)(bm * 128) * K;
    const fp16* srcB = Bhi + (size_t)(bn * 128) * K;

    float acc[4][8][4];
    #pragma unroll
    for (int mi = 0; mi < 4; mi++)
        #pragma unroll
        for (int ni = 0; ni < 8; ni++)
            #pragma unroll
            for (int j = 0; j < 4; j++) acc[mi][ni][j] = 0.f;

    gemm_core(sb, t, lane, wid, srcA, srcB, K, acc);

    const int wm = wid >> 1, wn = wid & 1;
    const int r0 = bm * 128 + wm * 64 + (lane >> 2);
    const int c0 = bn * 128 + wn * 64 + (lane & 3) * 2;
    #pragma unroll
    for (int mi = 0; mi < 4; mi++)
        #pragma unroll
        for (int rh = 0; rh < 2; rh++) {
            int row = r0 + mi * 16 + rh * 8;
            #pragma unroll
            for (int ni = 0; ni < 8; ni++) {
                int col = c0 + ni * 8;
                float v0 = acc[mi][ni][2 * rh];
                float v1 = acc[mi][ni][2 * rh + 1];
                if (flags & GF_BIAS) { v0 += bias[col]; v1 += bias[col + 1]; }
                if (flags & GF_GELU) {
                    v0 = 0.5f * v0 * (1.0f + erff(v0 * 0.70710678118654752f));
                    v1 = 0.5f * v1 * (1.0f + erff(v1 * 0.70710678118654752f));
                }
                if (flags & GF_RES16) {
                    __half2 rv = *(const __half2*)(resH + (size_t)row * N + col);
                    v0 += __low2float(rv); v1 += __high2float(rv);
                }
                if (flags & GF_HI) {
                    *(__half2*)(outHi + (size_t)row * N + col) =
                        __floats2half2_rn(v0, v1);
                } else {
                    float2* po = (float2*)(outF + (size_t)row * N + col);
                    *po = make_float2(v0, v1);
                }
            }
        }
}

// --------------------- tensor-core flash attention (batched) ----------------
#define A_STRIDE_B 144u
#define A_OP_B     9216u
#define A_STAGE_B  18432u
#define A_Q_B      9216u
#define ATTN_SMEM  (9216 + 2 * 18432)
#define KVS        (2 * Cdim)

__global__ __launch_bounds__(128) void attn_tc(AttnArgs args)
{
    extern __shared__ char smem[];
    const uint32_t sb = smem_u32(smem);
    const int zz = blockIdx.z;
    const int b = zz >> 1, br = zz & 1;
    const int h = blockIdx.y, qt = blockIdx.x;
    const int t = threadIdx.x, lane = t & 31, wid = t >> 5;

    const size_t qrow0 = (size_t)(b * Nseq + qt * 64);
    const fp16* gq = args.q[br] + qrow0 * Cdim + h * HD;
    const size_t krow0 = (size_t)b * Nseq;
    const fp16* gk = args.kv[br] + krow0 * KVS + h * HD;
    const fp16* gv = args.kv[br] + krow0 * KVS + Cdim + h * HD;

    #pragma unroll
    for (int i = 0; i < 4; i++) {
        int idx = t + (i << 7);
        int row = idx >> 3, c = idx & 7;
        cp16(sb + (uint32_t)row * A_STRIDE_B + (uint32_t)c * 16u,
             gq + (size_t)row * Cdim + c * 8);
    }
    CP_COMMIT();

    auto load_kv = [&](int kt) {
        uint32_t base = sb + A_Q_B + (uint32_t)(kt & 1) * A_STAGE_B;
        #pragma unroll
        for (int i = 0; i < 8; i++) {
            int idx = t + (i << 7);
            int op = idx >> 9, cid = idx & 511;
            int row = cid >> 3, c = cid & 7;
            const fp16* src = op ? gv : gk;
            cp16(base + (uint32_t)op * A_OP_B + (uint32_t)row * A_STRIDE_B
                      + (uint32_t)c * 16u,
                 src + (size_t)(kt * 64 + row) * KVS + c * 8);
        }
        CP_COMMIT();
    };

    load_kv(0);

    const uint32_t lrow = (uint32_t)(lane & 15);
    const uint32_t lc16 = (uint32_t)(lane >> 4) * 16u;

    uint32_t qh[4][4];
    float m_[2] = { -1e30f, -1e30f }, l_[2] = { 0.f, 0.f };
    float oacc[8][4];
    #pragma unroll
    for (int d = 0; d < 8; d++)
        #pragma unroll
        for (int j = 0; j < 4; j++) oacc[d][j] = 0.f;

    for (int kt = 0; kt < 16; kt++) {
        if (kt + 1 < 16) { load_kv(kt + 1); CP_WAIT1(); }
        else             { CP_WAIT0(); }
        __syncthreads();
        if (kt == 0) {
            uint32_t qoff = ((uint32_t)(wid * 16) + lrow) * A_STRIDE_B + lc16;
            #pragma unroll
            for (int k16 = 0; k16 < 4; k16++)
                ldsm4(qh[k16], sb + qoff + (uint32_t)k16 * 32u);
        }
        uint32_t base = sb + A_Q_B + (uint32_t)(kt & 1) * A_STAGE_B;

        float sacc[8][4];
        #pragma unroll
        for (int ni = 0; ni < 8; ni++)
            #pragma unroll
            for (int j = 0; j < 4; j++) sacc[ni][j] = 0.f;
        uint32_t koff = lrow * A_STRIDE_B + lc16;
        #pragma unroll
        for (int k16 = 0; k16 < 4; k16++) {
            uint32_t kb[4][4];
            #pragma unroll
            for (int g = 0; g < 4; g++)
                ldsm4(kb[g], base + koff + (uint32_t)g * 16u * A_STRIDE_B
                             + (uint32_t)k16 * 32u);
            #pragma unroll
            for (int ni = 0; ni < 8; ni++)
                mma16816(sacc[ni], qh[k16],
                         kb[ni >> 1][ni & 1], kb[ni >> 1][2 + (ni & 1)]);
        }
        #pragma unroll
        for (int ni = 0; ni < 8; ni++)
            #pragma unroll
            for (int j = 0; j < 4; j++) sacc[ni][j] *= 0.125f;

        float corr[2];
        #pragma unroll
        for (int rh = 0; rh < 2; rh++) {
            float mx = m_[rh];
            #pragma unroll
            for (int ni = 0; ni < 8; ni++) {
                mx = fmaxf(mx, sacc[ni][2 * rh]);
                mx = fmaxf(mx, sacc[ni][2 * rh + 1]);
            }
            mx = fmaxf(mx, __shfl_xor_sync(0xffffffffu, mx, 1));
            mx = fmaxf(mx, __shfl_xor_sync(0xffffffffu, mx, 2));
            float c = __expf(m_[rh] - mx);
            m_[rh] = mx;
            float sum = 0.f;
            #pragma unroll
            for (int ni = 0; ni < 8; ni++) {
                float p0 = __expf(sacc[ni][2 * rh] - mx);
                float p1 = __expf(sacc[ni][2 * rh + 1] - mx);
                sacc[ni][2 * rh] = p0; sacc[ni][2 * rh + 1] = p1;
                sum += p0 + p1;
            }
            sum += __shfl_xor_sync(0xffffffffu, sum, 1);
            sum += __shfl_xor_sync(0xffffffffu, sum, 2);
            l_[rh] = l_[rh] * c + sum;
            corr[rh] = c;
        }
        #pragma unroll
        for (int d = 0; d < 8; d++) {
            oacc[d][0] *= corr[0]; oacc[d][1] *= corr[0];
            oacc[d][2] *= corr[1]; oacc[d][3] *= corr[1];
        }

        uint32_t pa[4][4];
        #pragma unroll
        for (int k16 = 0; k16 < 4; k16++) {
            pa[k16][0] = pack_h2(sacc[2*k16][0],   sacc[2*k16][1]);
            pa[k16][1] = pack_h2(sacc[2*k16][2],   sacc[2*k16][3]);
            pa[k16][2] = pack_h2(sacc[2*k16+1][0], sacc[2*k16+1][1]);
            pa[k16][3] = pack_h2(sacc[2*k16+1][2], sacc[2*k16+1][3]);
        }

        #pragma unroll
        for (int k16 = 0; k16 < 4; k16++) {
            uint32_t vh[4][4];
            uint32_t vrow = ((uint32_t)(k16 * 16) + lrow) * A_STRIDE_B + lc16;
            #pragma unroll
            for (int dblk = 0; dblk < 4; dblk++)
                ldsm4t(vh[dblk], base + A_OP_B + vrow + (uint32_t)dblk * 32u);
            #pragma unroll
            for (int dblk = 0; dblk < 4; dblk++)
                #pragma unroll
                for (int sub = 0; sub < 2; sub++)
                    mma16816(oacc[dblk * 2 + sub], pa[k16],
                             vh[dblk][2*sub], vh[dblk][2*sub+1]);
        }
        __syncthreads();
    }

    float inv[2] = { 1.0f / l_[0], 1.0f / l_[1] };
    fp16* ohi = args.o[br];
    const size_t orow = qrow0 + wid * 16 + (lane >> 2);
    const int c0 = h * HD + (lane & 3) * 2;
    #pragma unroll
    for (int di = 0; di < 8; di++)
        #pragma unroll
        for (int rh = 0; rh < 2; rh++) {
            size_t row = orow + rh * 8;
            int col = c0 + di * 8;
            float v0 = oacc[di][2 * rh]     * inv[rh];
            float v1 = oacc[di][2 * rh + 1] * inv[rh];
            *(__half2*)(ohi + row * Cdim + col) = __floats2half2_rn(v0, v1);
        }
}

// ------------------------------- launch ------------------------------------
extern "C" void kernel_launch(void* const* d_in, const int* in_sizes, int n_in,
                              void* d_out, int out_size)
{
    const float* x1     = (const float*)d_in[0];
    const float* x2     = (const float*)d_in[1];
    const float* x3     = (const float*)d_in[2];
    const float* ln11_g = (const float*)d_in[3];
    const float* ln11_b = (const float*)d_in[4];
    const float* ln12_g = (const float*)d_in[5];
    const float* ln12_b = (const float*)d_in[6];
    const float* ln21_g = (const float*)d_in[7];
    const float* ln21_b = (const float*)d_in[8];
    const float* ln23_g = (const float*)d_in[9];
    const float* ln23_b = (const float*)d_in[10];
    const float* ln2_g  = (const float*)d_in[11];
    const float* ln2_b  = (const float*)d_in[12];
    const float* a1_wq  = (const float*)d_in[13];
    const float* a1_wk  = (const float*)d_in[14];
    const float* a1_wv  = (const float*)d_in[15];
    const float* a1_wp  = (const float*)d_in[16];
    const float* a1_bp  = (const float*)d_in[17];
    const float* a2_wq  = (const float*)d_in[18];
    const float* a2_wk  = (const float*)d_in[19];
    const float* a2_wv  = (const float*)d_in[20];
    const float* a2_wp  = (const float*)d_in[21];
    const float* a2_bp  = (const float*)d_in[22];
    const float* fc1_w  = (const float*)d_in[23];
    const float* fc1_b  = (const float*)d_in[24];
    const float* fc2_w  = (const float*)d_in[25];
    const float* fc2_b  = (const float*)d_in[26];
    float* out = (float*)d_out;

    fp16 *wT, *res16, *br2, *h_hi;
    fp16 *lnp, *qp, *kvp, *aop;
    cudaGetSymbolAddress((void**)&wT,    g_wT);
    cudaGetSymbolAddress((void**)&lnp,   g_ln);
    cudaGetSymbolAddress((void**)&qp,    g_q);
    cudaGetSymbolAddress((void**)&kvp,   g_kv);
    cudaGetSymbolAddress((void**)&aop,   g_ao);
    cudaGetSymbolAddress((void**)&h_hi,  g_h);
    cudaGetSymbolAddress((void**)&res16, g_res16);
    cudaGetSymbolAddress((void**)&br2,   g_br2);

    const size_t MC  = (size_t)Mrows * Cdim;
    fp16* ln0 = lnp;            // ln11(x1)
    fp16* ln1 = lnp + MC;       // ln12(x2)
    fp16* ln2o = lnp + 2 * MC;  // ln21(x1)
    fp16* ln3 = lnp + 3 * MC;   // ln23(x3)
    fp16* q0 = qp;            fp16* q1 = qp + MC;
    fp16* kv0 = kvp;          fp16* kv1 = kvp + 2 * MC;
    fp16* ao0 = aop;          fp16* ao1 = aop + MC;

    cudaFuncSetAttribute(qkv_tc,
                         cudaFuncAttributeMaxDynamicSharedMemorySize, GEMM_SMEM);
    cudaFuncSetAttribute(proj_tc,
                         cudaFuncAttributeMaxDynamicSharedMemorySize, GEMM_SMEM);
    cudaFuncSetAttribute(gemm_tc,
                         cudaFuncAttributeMaxDynamicSharedMemorySize, GEMM_SMEM);
    cudaFuncSetAttribute(attn_tc,
                         cudaFuncAttributeMaxDynamicSharedMemorySize, ATTN_SMEM);

    const size_t MEG = 1u << 20;

    // 0: ln4 — all four input LayerNorms
    Ln4Args la;
    la.x[0] = x1; la.x[1] = x2; la.x[2] = x1; la.x[3] = x3;
    la.g[0] = ln11_g; la.g[1] = ln12_g; la.g[2] = ln21_g; la.g[3] = ln23_g;
    la.b[0] = ln11_b; la.b[1] = ln12_b; la.b[2] = ln21_b; la.b[3] = ln23_b;
    la.o[0] = ln0; la.o[1] = ln1; la.o[2] = ln2o; la.o[3] = ln3;
    ln4_kernel<<<4 * Mrows, 256>>>(la);

    // 1: wconv6 — qkv weights both branches
    W6Args wa;
    wa.w[0] = a1_wq; wa.w[1] = a1_wk; wa.w[2] = a1_wv;
    wa.w[3] = a2_wq; wa.w[4] = a2_wk; wa.w[5] = a2_wv;
    for (int i = 0; i < 6; i++) wa.d[i] = wT + i * MEG;
    wconv6_kernel<<<dim3(Cdim / 32, Cdim / 32, 6), 256>>>(wa);

    // 2: wconv6 (reuse kernel) — wp1, wp2 + fc weights head-start? wp only (z=2)
    W6Args wp;
    wp.w[0] = a1_wp; wp.w[1] = a2_wp;
    wp.w[2] = a1_wp; wp.w[3] = a1_wp; wp.w[4] = a1_wp; wp.w[5] = a1_wp; // unused z
    wp.d[0] = wT + 6 * MEG; wp.d[1] = wT + 7 * MEG;
    wp.d[2] = wT + 6 * MEG; wp.d[3] = wT + 6 * MEG;
    wp.d[4] = wT + 6 * MEG; wp.d[5] = wT + 6 * MEG;
    wconv6_kernel<<<dim3(Cdim / 32, Cdim / 32, 2), 256>>>(wp);

    // 3: batched QKV (6 GEMMs) <- profiler lands here
    QkvArgs qa;
    qa.A[0] = ln0; qa.A[1] = ln1; qa.A[2] = ln1;
    qa.A[3] = ln2o; qa.A[4] = ln3; qa.A[5] = ln3;
    for (int i = 0; i < 6; i++) qa.B[i] = wT + i * MEG;
    qa.out[0] = q0;  qa.ostride[0] = Cdim;
    qa.out[1] = kv0; qa.ostride[1] = KVS;
    qa.out[2] = kv0 + Cdim; qa.ostride[2] = KVS;
    qa.out[3] = q1;  qa.ostride[3] = Cdim;
    qa.out[4] = kv1; qa.ostride[4] = KVS;
    qa.out[5] = kv1 + Cdim; qa.ostride[5] = KVS;
    qkv_tc<<<dim3(Cdim / 128, Mrows / 128, 6), 128, GEMM_SMEM>>>(qa);

    // 4: batched attention (both branches)
    AttnArgs aa;
    aa.q[0] = q0; aa.q[1] = q1;
    aa.kv[0] = kv0; aa.kv[1] = kv1;
    aa.o[0] = ao0; aa.o[1] = ao1;
    attn_tc<<<dim3(Nseq / 64, NH, 2 * Bsz), 128, ATTN_SMEM>>>(aa);

    // 5: batched projections (z=0: +x1 residual -> res16; z=1: -> br2)
    ProjArgs pa;
    pa.A[0] = ao0; pa.A[1] = ao1;
    pa.B[0] = wT + 6 * MEG; pa.B[1] = wT + 7 * MEG;
    pa.bias[0] = a1_bp; pa.bias[1] = a2_bp;
    pa.resF = x1;
    pa.out[0] = res16; pa.out[1] = br2;
    proj_tc<<<dim3(Cdim / 128, Mrows / 128, 2), 128, GEMM_SMEM>>>(pa);

    // 6-7: fc weight conversions
    wconv_kernel<<<dim3(HidD / 32, Cdim / 32), 256>>>(fc1_w, wT + 8 * MEG, Cdim, HidD);
    wconv_kernel<<<dim3(Cdim / 32, HidD / 32), 256>>>(fc2_w, wT + 12 * MEG, HidD, Cdim);

    // 8: fused residual sum + LN2
    ln16_sum_kernel<<<Mrows, 256>>>(res16, br2, ln2_g, ln2_b, ln0);

    // 9: fc1 (+bias, gelu)
    gemm_tc<<<dim3(HidD / 128, Mrows / 128), 128, GEMM_SMEM>>>(
        ln0, wT + 8 * MEG, fc1_b, nullptr, nullptr, h_hi,
        Mrows, HidD, Cdim, GF_BIAS | GF_GELU | GF_HI);

    // 10: fc2 (+bias, +res16) -> fp32 out
    gemm_tc<<<dim3(Cdim / 128, Mrows / 128), 128, GEMM_SMEM>>>(
        h_hi, wT + 12 * MEG, fc2_b, res16, out, nullptr,
        Mrows, Cdim, HidD, GF_BIAS | GF_RES16);
}